// round 11
// baseline (speedup 1.0000x reference)
#include <cuda_runtime.h>
#include <cuda_fp16.h>
#include <math.h>
#include <stdint.h>

#define HID 128
#define BM  128
#define THREADS 256
#define NPB 32
#define N_NODES_MAX 100000

__device__ __half g_hsrc[N_NODES_MAX * HID];   // node_emb @ W1[0:128]
__device__ __half g_htgt[N_NODES_MAX * HID];   // node_emb @ W1[128:256]
__device__ __half g_w2h[4 * 4096];             // W2 chunks, fragment-major
__device__ float  g_wx[2][16 * 128];
__device__ float  g_wp[2][3 * 128];
__device__ float  g_cb[2][128];

// fast silu: v * sigmoid(v) = 0.5v(1 + tanh(v/2))
__device__ __forceinline__ float silu(float v) {
    float th;
    asm("tanh.approx.f32 %0, %1;" : "=f"(th) : "f"(v * 0.5f));
    return fmaf(0.5f * v, th, 0.5f * v);
}
__device__ __forceinline__ void mma16(float4& d, uint32_t a0, uint32_t a1,
                                      uint32_t a2, uint32_t a3,
                                      uint32_t b0, uint32_t b1) {
    asm volatile(
        "mma.sync.aligned.m16n8k16.row.col.f32.f16.f16.f32 "
        "{%0,%1,%2,%3},{%4,%5,%6,%7},{%8,%9},{%0,%1,%2,%3};"
        : "+f"(d.x), "+f"(d.y), "+f"(d.z), "+f"(d.w)
        : "r"(a0), "r"(a1), "r"(a2), "r"(a3), "r"(b0), "r"(b1));
}
__device__ __forceinline__ void ldm4(uint32_t& a0, uint32_t& a1,
                                     uint32_t& a2, uint32_t& a3, uint32_t addr) {
    asm volatile("ldmatrix.sync.aligned.m8n8.x4.shared.b16 {%0,%1,%2,%3},[%4];"
                 : "=r"(a0), "=r"(a1), "=r"(a2), "=r"(a3) : "r"(addr));
}
// swizzled 16B-chunk position within a 256B row (stays inside its 128B half)
__device__ __forceinline__ int sw_pos(int row, int cc) {
    return (cc & 8) + ((cc & 7) ^ (row & 7));
}

// ------------- Kernel 1: weight products ------------------------------------
__global__ void weight_prod(const float* __restrict__ Wa,
                            const float* __restrict__ ba,
                            const float* __restrict__ Wp,
                            const float* __restrict__ bp,
                            const float* __restrict__ W1) {
    __shared__ float swa[16 * 128];
    __shared__ float swp[3 * 128];
    __shared__ float sb[128];
    int p = blockIdx.x;
    int j = threadIdx.x;
    for (int i = j; i < 16 * 128; i += 128) swa[i] = Wa[i];
    for (int i = j; i < 3 * 128; i += 128) swp[i] = Wp[i];
    sb[j] = ba[j] + bp[j];
    __syncthreads();

    float ax[16];
#pragma unroll
    for (int i = 0; i < 16; i++) ax[i] = 0.f;
    float ap[3] = {0.f, 0.f, 0.f};
    float ac = 0.f;
    for (int k = 0; k < 128; k++) {
        float w = W1[(p * 128 + k) * 128 + j];
#pragma unroll
        for (int i = 0; i < 16; i++) ax[i] += swa[i * 128 + k] * w;
#pragma unroll
        for (int i = 0; i < 3; i++) ap[i] += swp[i * 128 + k] * w;
        ac += sb[k] * w;
    }
#pragma unroll
    for (int i = 0; i < 16; i++) g_wx[p][i * 128 + j] = ax[i];
#pragma unroll
    for (int i = 0; i < 3; i++) g_wp[p][i * 128 + j] = ap[i];
    g_cb[p][j] = ac;
}

// ------------- Kernel 2: per-node h_src / h_tgt ------------------------------
__global__ void node_h_kernel(const float* __restrict__ x,
                              const float* __restrict__ pos, int N) {
    int j = threadIdx.x;
    float wx0[16], wx1[16], wp0[3], wp1[3];
#pragma unroll
    for (int i = 0; i < 16; i++) {
        wx0[i] = g_wx[0][i * 128 + j];
        wx1[i] = g_wx[1][i * 128 + j];
    }
#pragma unroll
    for (int i = 0; i < 3; i++) {
        wp0[i] = g_wp[0][i * 128 + j];
        wp1[i] = g_wp[1][i * 128 + j];
    }
    float c0 = g_cb[0][j], c1 = g_cb[1][j];

    __shared__ float xs[NPB][16];
    __shared__ float ps[NPB][3];
    int n0 = blockIdx.x * NPB;
    for (int i = j; i < NPB * 16; i += 128) {
        int n = n0 + (i >> 4);
        xs[i >> 4][i & 15] = (n < N) ? x[n * 16 + (i & 15)] : 0.0f;
    }
    for (int i = j; i < NPB * 3; i += 128) {
        int n = n0 + i / 3;
        ps[i / 3][i % 3] = (n < N) ? pos[n * 3 + i % 3] : 0.0f;
    }
    __syncthreads();
    for (int n = 0; n < NPB; n++) {
        if (n0 + n >= N) break;
        float s0 = c0, s1 = c1;
#pragma unroll
        for (int i = 0; i < 16; i++) {
            s0 += xs[n][i] * wx0[i];
            s1 += xs[n][i] * wx1[i];
        }
#pragma unroll
        for (int i = 0; i < 3; i++) {
            s0 += ps[n][i] * wp0[i];
            s1 += ps[n][i] * wp1[i];
        }
        g_hsrc[(n0 + n) * HID + j] = __float2half(s0);
        g_htgt[(n0 + n) * HID + j] = __float2half(s1);
    }
}

// ------------- Kernel 3: W2 fragment-major packing ---------------------------
__global__ void prep_w2(const float* __restrict__ W2) {
    int c = blockIdx.x;
    __half* dst = g_w2h + c * 4096;
    for (int idx = threadIdx.x; idx < 4096; idx += 256) {
        int u = idx & 3;
        int t = (idx >> 2) & 3;
        int n = (idx >> 4) & 127;
        int step = idx >> 11;
        int kl = step * 16 + ((u >> 1) << 3) + 2 * t + (u & 1);
        dst[idx] = __float2half(W2[(c * 32 + kl) * 128 + n]);
    }
}

// ------------- Kernel 4: edge MLP (3 CTAs/SM, HADD2 conv) -------------------
__global__ void __launch_bounds__(THREADS, 3)
edge_mlp6(const float* __restrict__ pos, const int* __restrict__ ei,
          const float* __restrict__ W1, const float* __restrict__ b1,
          const float* __restrict__ b2,
          const float* __restrict__ W3, const float* __restrict__ b3,
          float* __restrict__ out, int E) {
    __shared__ __align__(16) __half hs[BM * HID];        // 32 KB, swizzled
    __shared__ __align__(16) float part[2 * BM * 4];     // 4 KB
    __shared__ int   soff[BM], doff[BM];
    __shared__ float dist[BM];
    __shared__ float w256[128], sb1[128], sb2[128], w3s[512], b3s[4];

    const uint32_t hsu = (uint32_t)__cvta_generic_to_shared(hs);
    const int tid  = threadIdx.x;
    const int lane = tid & 31;
    const int wid  = tid >> 5;
    const int m_base = (wid >> 1) * 32;      // 4 m-groups of 32 rows
    const int n_warp = (wid & 1) * 64;       // 2 n-groups of 64 cols
    const int g = lane >> 2;
    const int t = lane & 3;
    const int tile0 = blockIdx.x * BM;

    // ---- setup ----
    if (tid < BM) {
        int ge = tile0 + tid; if (ge >= E) ge = E - 1;
        int s = ei[ge], d = ei[E + ge];
        soff[tid] = s * HID;
        doff[tid] = d * HID;
        float dx = pos[s * 3 + 0] - pos[d * 3 + 0];
        float dy = pos[s * 3 + 1] - pos[d * 3 + 1];
        float dz = pos[s * 3 + 2] - pos[d * 3 + 2];
        dist[tid] = sqrtf(dx * dx + dy * dy + dz * dz);
    } else {
        int c = tid - BM;
        w256[c] = W1[256 * 128 + c];
        sb1[c] = b1[c];
        sb2[c] = b2[c];
    }
    for (int i = tid; i < 512; i += THREADS) w3s[i] = W3[i];
    if (tid < 4) b3s[tid] = b3[tid];
    __syncthreads();

    // ---- conv: coalesced gather, fp16 pre-sum, f32 silu -> hs --------------
    {
        const int g2 = lane >> 3;            // row within quad
        const int sub = lane & 7;            // 16B chunk within half-line
        const int rbase = wid * 16;
#pragma unroll
        for (int it = 0; it < 8; it++) {
            int half = it & 1;
            int rq = it >> 1;                // 0..3
            int row = rbase + rq * 4 + g2;
            uint4 av = *(const uint4*)(g_hsrc + soff[row] + half * 64 + sub * 8);
            uint4 bv = *(const uint4*)(g_htgt + doff[row] + half * 64 + sub * 8);
            float dd = dist[row];
            int cc = half * 8 + sub;
            int c0 = cc * 8;
            float4 wA = *(const float4*)&w256[c0];
            float4 wB = *(const float4*)&w256[c0 + 4];
            float4 bA = *(const float4*)&sb1[c0];
            float4 bB = *(const float4*)&sb1[c0 + 4];
            const __half2* ah = (const __half2*)&av;
            const __half2* bh = (const __half2*)&bv;
            float2 f0 = __half22float2(__hadd2(ah[0], bh[0]));
            float2 f1 = __half22float2(__hadd2(ah[1], bh[1]));
            float2 f2 = __half22float2(__hadd2(ah[2], bh[2]));
            float2 f3 = __half22float2(__hadd2(ah[3], bh[3]));
            __half2 o0 = __floats2half2_rn(silu(f0.x + fmaf(dd, wA.x, bA.x)),
                                           silu(f0.y + fmaf(dd, wA.y, bA.y)));
            __half2 o1 = __floats2half2_rn(silu(f1.x + fmaf(dd, wA.z, bA.z)),
                                           silu(f1.y + fmaf(dd, wA.w, bA.w)));
            __half2 o2 = __floats2half2_rn(silu(f2.x + fmaf(dd, wB.x, bB.x)),
                                           silu(f2.y + fmaf(dd, wB.y, bB.y)));
            __half2 o3 = __floats2half2_rn(silu(f3.x + fmaf(dd, wB.z, bB.z)),
                                           silu(f3.y + fmaf(dd, wB.w, bB.w)));
            uint4 ov;
            ov.x = *(uint32_t*)&o0; ov.y = *(uint32_t*)&o1;
            ov.z = *(uint32_t*)&o2; ov.w = *(uint32_t*)&o3;
            *(uint4*)((char*)hs + row * 256 + (sw_pos(row, cc) << 4)) = ov;
        }
    }
    __syncthreads();

    // ---- GEMM2: h1 @ W2 (K=128), warp tile 32x64, B-frags in 2 groups ------
    float4 acc[2][8];
#pragma unroll
    for (int i = 0; i < 2; i++)
#pragma unroll
        for (int j = 0; j < 8; j++) acc[i][j] = make_float4(0.f, 0.f, 0.f, 0.f);
#pragma unroll
    for (int c = 0; c < 4; c++) {
        const __half* Bp = g_w2h + c * 4096;
#pragma unroll
        for (int s = 0; s < 2; s++) {
            int sg = c * 2 + s;
            // A fragments for both m halves first
            uint32_t a0[4], a1[4];
            {
                int cc = sg * 2 + (lane >> 4);
                int lr0 = m_base + (lane & 7) + (lane & 8);
                ldm4(a0[0], a0[1], a0[2], a0[3],
                     hsu + lr0 * 256 + (sw_pos(lr0, cc) << 4));
                int lr1 = lr0 + 16;
                ldm4(a1[0], a1[1], a1[2], a1[3],
                     hsu + lr1 * 256 + (sw_pos(lr1, cc) << 4));
            }
            // B group 1: ni 0..3
            {
                uint2 bf[4];
#pragma unroll
                for (int ni = 0; ni < 4; ni++) {
                    int n = n_warp + ni * 8 + g;
                    bf[ni] = *(const uint2*)(Bp + (((s * 128 + n) << 2) + t) * 4);
                }
#pragma unroll
                for (int ni = 0; ni < 4; ni++) {
                    mma16(acc[0][ni], a0[0], a0[1], a0[2], a0[3], bf[ni].x, bf[ni].y);
                    mma16(acc[1][ni], a1[0], a1[1], a1[2], a1[3], bf[ni].x, bf[ni].y);
                }
            }
            // B group 2: ni 4..7
            {
                uint2 bf[4];
#pragma unroll
                for (int ni = 0; ni < 4; ni++) {
                    int n = n_warp + (ni + 4) * 8 + g;
                    bf[ni] = *(const uint2*)(Bp + (((s * 128 + n) << 2) + t) * 4);
                }
#pragma unroll
                for (int ni = 0; ni < 4; ni++) {
                    mma16(acc[0][ni + 4], a0[0], a0[1], a0[2], a0[3], bf[ni].x, bf[ni].y);
                    mma16(acc[1][ni + 4], a1[0], a1[1], a1[2], a1[3], bf[ni].x, bf[ni].y);
                }
            }
        }
    }

    // ---- epilogue: silu(D2+b2), GEMM3 dot, shfl reduce over quad -----------
#pragma unroll
    for (int mi = 0; mi < 2; mi++) {
        float4 plo = make_float4(0.f, 0.f, 0.f, 0.f);
        float4 phi = make_float4(0.f, 0.f, 0.f, 0.f);
#pragma unroll
        for (int ni = 0; ni < 8; ni++) {
            int c0 = n_warp + ni * 8 + 2 * t;
            float4 a = acc[mi][ni];
            float v0 = silu(a.x + sb2[c0]);
            float v1 = silu(a.y + sb2[c0 + 1]);
            float v2 = silu(a.z + sb2[c0]);
            float v3 = silu(a.w + sb2[c0 + 1]);
            float4 w0 = *(const float4*)&w3s[c0 * 4];
            float4 w1 = *(const float4*)&w3s[(c0 + 1) * 4];
            plo.x += v0 * w0.x + v1 * w1.x;
            plo.y += v0 * w0.y + v1 * w1.y;
            plo.z += v0 * w0.z + v1 * w1.z;
            plo.w += v0 * w0.w + v1 * w1.w;
            phi.x += v2 * w0.x + v3 * w1.x;
            phi.y += v2 * w0.y + v3 * w1.y;
            phi.z += v2 * w0.z + v3 * w1.z;
            phi.w += v2 * w0.w + v3 * w1.w;
        }
#pragma unroll
        for (int m = 1; m <= 2; m <<= 1) {
            plo.x += __shfl_xor_sync(0xffffffffu, plo.x, m);
            plo.y += __shfl_xor_sync(0xffffffffu, plo.y, m);
            plo.z += __shfl_xor_sync(0xffffffffu, plo.z, m);
            plo.w += __shfl_xor_sync(0xffffffffu, plo.w, m);
            phi.x += __shfl_xor_sync(0xffffffffu, phi.x, m);
            phi.y += __shfl_xor_sync(0xffffffffu, phi.y, m);
            phi.z += __shfl_xor_sync(0xffffffffu, phi.z, m);
            phi.w += __shfl_xor_sync(0xffffffffu, phi.w, m);
        }
        if (t == 0) {
            int r = m_base + mi * 16 + g;
            *(float4*)&part[((wid & 1) * BM + r) * 4] = plo;
            *(float4*)&part[((wid & 1) * BM + r + 8) * 4] = phi;
        }
    }
    __syncthreads();

    if (tid < BM) {
        int ge = tile0 + tid;
        float4 p0 = *(const float4*)&part[tid * 4];
        float4 p1 = *(const float4*)&part[(BM + tid) * 4];
        float4 o;
        o.x = p0.x + p1.x + b3s[0];
        o.y = p0.y + p1.y + b3s[1];
        o.z = p0.z + p1.z + b3s[2];
        o.w = p0.w + p1.w + b3s[3];
        if (ge < E) *(float4*)&out[ge * 4] = o;
    }
}

// ---------------------------------------------------------------------------
extern "C" void kernel_launch(void* const* d_in, const int* in_sizes, int n_in,
                              void* d_out, int out_size) {
    const float* x   = (const float*)d_in[0];
    const float* pos = (const float*)d_in[1];
    const int*   ei  = (const int*)  d_in[2];
    const float* Wa  = (const float*)d_in[3];
    const float* ba  = (const float*)d_in[4];
    const float* Wp  = (const float*)d_in[5];
    const float* bp  = (const float*)d_in[6];
    const float* W1  = (const float*)d_in[7];
    const float* b1  = (const float*)d_in[8];
    const float* W2  = (const float*)d_in[9];
    const float* b2  = (const float*)d_in[10];
    const float* W3  = (const float*)d_in[11];
    const float* b3  = (const float*)d_in[12];
    float* out = (float*)d_out;

    int N = in_sizes[0] / 16;
    int E = in_sizes[2] / 2;

    weight_prod<<<2, 128>>>(Wa, ba, Wp, bp, W1);
    prep_w2<<<4, 256>>>(W2);
    node_h_kernel<<<(N + NPB - 1) / NPB, 128>>>(x, pos, N);
    edge_mlp6<<<(E + BM - 1) / BM, THREADS>>>(
        pos, ei, W1, b1, b2, W3, b3, out, E);
}

// round 12
// speedup vs baseline: 2.3265x; 2.3265x over previous
#include <cuda_runtime.h>
#include <cuda_fp16.h>
#include <math.h>
#include <stdint.h>

#define HID 128
#define BM  128
#define THREADS 512
#define NPB 32
#define N_NODES_MAX 100000

__device__ __half g_hsrc[N_NODES_MAX * HID];   // node_emb @ W1[0:128]
__device__ __half g_htgt[N_NODES_MAX * HID];   // node_emb @ W1[128:256]
__device__ __half g_w2h[4 * 4096];             // W2 chunks, fragment-major
__device__ float  g_wx[2][16 * 128];
__device__ float  g_wp[2][3 * 128];
__device__ float  g_cb[2][128];

// fast silu: v * sigmoid(v) = 0.5v(1 + tanh(v/2))
__device__ __forceinline__ float silu(float v) {
    float th;
    asm("tanh.approx.f32 %0, %1;" : "=f"(th) : "f"(v * 0.5f));
    return fmaf(0.5f * v, th, 0.5f * v);
}
__device__ __forceinline__ void mma16(float4& d, uint32_t a0, uint32_t a1,
                                      uint32_t a2, uint32_t a3,
                                      uint32_t b0, uint32_t b1) {
    asm volatile(
        "mma.sync.aligned.m16n8k16.row.col.f32.f16.f16.f32 "
        "{%0,%1,%2,%3},{%4,%5,%6,%7},{%8,%9},{%0,%1,%2,%3};"
        : "+f"(d.x), "+f"(d.y), "+f"(d.z), "+f"(d.w)
        : "r"(a0), "r"(a1), "r"(a2), "r"(a3), "r"(b0), "r"(b1));
}
__device__ __forceinline__ void ldm4(uint32_t& a0, uint32_t& a1,
                                     uint32_t& a2, uint32_t& a3, uint32_t addr) {
    asm volatile("ldmatrix.sync.aligned.m8n8.x4.shared.b16 {%0,%1,%2,%3},[%4];"
                 : "=r"(a0), "=r"(a1), "=r"(a2), "=r"(a3) : "r"(addr));
}
// swizzled 16B-chunk position within a 256B row (stays inside its 128B half)
__device__ __forceinline__ int sw_pos(int row, int cc) {
    return (cc & 8) + ((cc & 7) ^ (row & 7));
}

// ------------- Kernel 1: weight products ------------------------------------
__global__ void weight_prod(const float* __restrict__ Wa,
                            const float* __restrict__ ba,
                            const float* __restrict__ Wp,
                            const float* __restrict__ bp,
                            const float* __restrict__ W1) {
    __shared__ float swa[16 * 128];
    __shared__ float swp[3 * 128];
    __shared__ float sb[128];
    int p = blockIdx.x;
    int j = threadIdx.x;
    for (int i = j; i < 16 * 128; i += 128) swa[i] = Wa[i];
    for (int i = j; i < 3 * 128; i += 128) swp[i] = Wp[i];
    sb[j] = ba[j] + bp[j];
    __syncthreads();

    float ax[16];
#pragma unroll
    for (int i = 0; i < 16; i++) ax[i] = 0.f;
    float ap[3] = {0.f, 0.f, 0.f};
    float ac = 0.f;
    for (int k = 0; k < 128; k++) {
        float w = W1[(p * 128 + k) * 128 + j];
#pragma unroll
        for (int i = 0; i < 16; i++) ax[i] += swa[i * 128 + k] * w;
#pragma unroll
        for (int i = 0; i < 3; i++) ap[i] += swp[i * 128 + k] * w;
        ac += sb[k] * w;
    }
#pragma unroll
    for (int i = 0; i < 16; i++) g_wx[p][i * 128 + j] = ax[i];
#pragma unroll
    for (int i = 0; i < 3; i++) g_wp[p][i * 128 + j] = ap[i];
    g_cb[p][j] = ac;
}

// ------------- Kernel 2: per-node h_src / h_tgt ------------------------------
__global__ void node_h_kernel(const float* __restrict__ x,
                              const float* __restrict__ pos, int N) {
    int j = threadIdx.x;
    float wx0[16], wx1[16], wp0[3], wp1[3];
#pragma unroll
    for (int i = 0; i < 16; i++) {
        wx0[i] = g_wx[0][i * 128 + j];
        wx1[i] = g_wx[1][i * 128 + j];
    }
#pragma unroll
    for (int i = 0; i < 3; i++) {
        wp0[i] = g_wp[0][i * 128 + j];
        wp1[i] = g_wp[1][i * 128 + j];
    }
    float c0 = g_cb[0][j], c1 = g_cb[1][j];

    __shared__ float xs[NPB][16];
    __shared__ float ps[NPB][3];
    int n0 = blockIdx.x * NPB;
    for (int i = j; i < NPB * 16; i += 128) {
        int n = n0 + (i >> 4);
        xs[i >> 4][i & 15] = (n < N) ? x[n * 16 + (i & 15)] : 0.0f;
    }
    for (int i = j; i < NPB * 3; i += 128) {
        int n = n0 + i / 3;
        ps[i / 3][i % 3] = (n < N) ? pos[n * 3 + i % 3] : 0.0f;
    }
    __syncthreads();
    for (int n = 0; n < NPB; n++) {
        if (n0 + n >= N) break;
        float s0 = c0, s1 = c1;
#pragma unroll
        for (int i = 0; i < 16; i++) {
            s0 += xs[n][i] * wx0[i];
            s1 += xs[n][i] * wx1[i];
        }
#pragma unroll
        for (int i = 0; i < 3; i++) {
            s0 += ps[n][i] * wp0[i];
            s1 += ps[n][i] * wp1[i];
        }
        g_hsrc[(n0 + n) * HID + j] = __float2half(s0);
        g_htgt[(n0 + n) * HID + j] = __float2half(s1);
    }
}

// ------------- Kernel 3: W2 fragment-major packing ---------------------------
__global__ void prep_w2(const float* __restrict__ W2) {
    int c = blockIdx.x;
    __half* dst = g_w2h + c * 4096;
    for (int idx = threadIdx.x; idx < 4096; idx += 256) {
        int u = idx & 3;
        int t = (idx >> 2) & 3;
        int n = (idx >> 4) & 127;
        int step = idx >> 11;
        int kl = step * 16 + ((u >> 1) << 3) + 2 * t + (u & 1);
        dst[idx] = __float2half(W2[(c * 32 + kl) * 128 + n]);
    }
}

// ------------- Kernel 4: edge MLP (512 thr, 32x32 tiles, 2 CTA/SM) ----------
__global__ void __launch_bounds__(THREADS, 2)
edge_mlp7(const float* __restrict__ pos, const int* __restrict__ ei,
          const float* __restrict__ W1, const float* __restrict__ b1,
          const float* __restrict__ b2,
          const float* __restrict__ W3, const float* __restrict__ b3,
          float* __restrict__ out, int E) {
    __shared__ __align__(16) __half hs[BM * HID];        // 32 KB, swizzled
    __shared__ __align__(16) float part[4 * BM * 4];     // 8 KB
    __shared__ int   soff[BM], doff[BM];
    __shared__ float dist[BM];
    __shared__ float w256[128], sb1[128], sb2[128], w3s[512], b3s[4];

    const uint32_t hsu = (uint32_t)__cvta_generic_to_shared(hs);
    const int tid  = threadIdx.x;
    const int lane = tid & 31;
    const int wid  = tid >> 5;               // 0..15
    const int m_base = (wid & 3) * 32;       // 4 m-groups of 32 rows
    const int n_warp = (wid >> 2) * 32;      // 4 n-groups of 32 cols
    const int g = lane >> 2;
    const int t = lane & 3;
    const int tile0 = blockIdx.x * BM;

    // ---- setup ----
    if (tid < BM) {
        int ge = tile0 + tid; if (ge >= E) ge = E - 1;
        int s = ei[ge], d = ei[E + ge];
        soff[tid] = s * HID;
        doff[tid] = d * HID;
        float dx = pos[s * 3 + 0] - pos[d * 3 + 0];
        float dy = pos[s * 3 + 1] - pos[d * 3 + 1];
        float dz = pos[s * 3 + 2] - pos[d * 3 + 2];
        dist[tid] = sqrtf(dx * dx + dy * dy + dz * dz);
    } else if (tid < 2 * BM) {
        int c = tid - BM;
        w256[c] = W1[256 * 128 + c];
        sb1[c] = b1[c];
        sb2[c] = b2[c];
    } else {
        int i = tid - 2 * BM;                 // 0..255
        w3s[i] = W3[i];
        w3s[i + 256] = W3[i + 256];
        if (i < 4) b3s[i] = b3[i];
    }
    __syncthreads();

    // ---- conv: coalesced gather, fp16 pre-sum, f32 silu -> hs --------------
    // per warp: 8 rows; per instr: 4 rows x one 128B half-line (8 lanes each)
    {
        const int g2 = lane >> 3;            // row within quad
        const int sub = lane & 7;            // 16B chunk within half-line
        const int rbase = wid * 8;
#pragma unroll
        for (int it = 0; it < 4; it++) {
            int half = it & 1;
            int rq = it >> 1;                // 0..1
            int row = rbase + rq * 4 + g2;
            uint4 av = *(const uint4*)(g_hsrc + soff[row] + half * 64 + sub * 8);
            uint4 bv = *(const uint4*)(g_htgt + doff[row] + half * 64 + sub * 8);
            float dd = dist[row];
            int cc = half * 8 + sub;
            int c0 = cc * 8;
            float4 wA = *(const float4*)&w256[c0];
            float4 wB = *(const float4*)&w256[c0 + 4];
            float4 bA = *(const float4*)&sb1[c0];
            float4 bB = *(const float4*)&sb1[c0 + 4];
            const __half2* ah = (const __half2*)&av;
            const __half2* bh = (const __half2*)&bv;
            float2 f0 = __half22float2(__hadd2(ah[0], bh[0]));
            float2 f1 = __half22float2(__hadd2(ah[1], bh[1]));
            float2 f2 = __half22float2(__hadd2(ah[2], bh[2]));
            float2 f3 = __half22float2(__hadd2(ah[3], bh[3]));
            __half2 o0 = __floats2half2_rn(silu(f0.x + fmaf(dd, wA.x, bA.x)),
                                           silu(f0.y + fmaf(dd, wA.y, bA.y)));
            __half2 o1 = __floats2half2_rn(silu(f1.x + fmaf(dd, wA.z, bA.z)),
                                           silu(f1.y + fmaf(dd, wA.w, bA.w)));
            __half2 o2 = __floats2half2_rn(silu(f2.x + fmaf(dd, wB.x, bB.x)),
                                           silu(f2.y + fmaf(dd, wB.y, bB.y)));
            __half2 o3 = __floats2half2_rn(silu(f3.x + fmaf(dd, wB.z, bB.z)),
                                           silu(f3.y + fmaf(dd, wB.w, bB.w)));
            uint4 ov;
            ov.x = *(uint32_t*)&o0; ov.y = *(uint32_t*)&o1;
            ov.z = *(uint32_t*)&o2; ov.w = *(uint32_t*)&o3;
            *(uint4*)((char*)hs + row * 256 + (sw_pos(row, cc) << 4)) = ov;
        }
    }
    __syncthreads();

    // ---- GEMM2: h1 @ W2 (K=128), warp tile 32x32, B-frags from global ------
    float4 acc[2][4];
#pragma unroll
    for (int i = 0; i < 2; i++)
#pragma unroll
        for (int j = 0; j < 4; j++) acc[i][j] = make_float4(0.f, 0.f, 0.f, 0.f);
#pragma unroll
    for (int c = 0; c < 4; c++) {
        const __half* Bp = g_w2h + c * 4096;
#pragma unroll
        for (int s = 0; s < 2; s++) {
            int sg = c * 2 + s;
            uint2 bf[4];
#pragma unroll
            for (int ni = 0; ni < 4; ni++) {
                int n = n_warp + ni * 8 + g;
                bf[ni] = *(const uint2*)(Bp + (((s * 128 + n) << 2) + t) * 4);
            }
#pragma unroll
            for (int mi = 0; mi < 2; mi++) {
                int lrow = m_base + mi * 16 + (lane & 7) + (lane & 8);
                int cc = sg * 2 + (lane >> 4);
                uint32_t addr = hsu + lrow * 256 + (sw_pos(lrow, cc) << 4);
                uint32_t a0, a1, a2, a3;
                ldm4(a0, a1, a2, a3, addr);
#pragma unroll
                for (int ni = 0; ni < 4; ni++)
                    mma16(acc[mi][ni], a0, a1, a2, a3, bf[ni].x, bf[ni].y);
            }
        }
    }

    // ---- epilogue: silu(D2+b2), GEMM3 dot, shfl reduce over quad -----------
#pragma unroll
    for (int mi = 0; mi < 2; mi++) {
        float4 plo = make_float4(0.f, 0.f, 0.f, 0.f);
        float4 phi = make_float4(0.f, 0.f, 0.f, 0.f);
#pragma unroll
        for (int ni = 0; ni < 4; ni++) {
            int c0 = n_warp + ni * 8 + 2 * t;
            float4 a = acc[mi][ni];
            float v0 = silu(a.x + sb2[c0]);
            float v1 = silu(a.y + sb2[c0 + 1]);
            float v2 = silu(a.z + sb2[c0]);
            float v3 = silu(a.w + sb2[c0 + 1]);
            float4 w0 = *(const float4*)&w3s[c0 * 4];
            float4 w1 = *(const float4*)&w3s[(c0 + 1) * 4];
            plo.x += v0 * w0.x + v1 * w1.x;
            plo.y += v0 * w0.y + v1 * w1.y;
            plo.z += v0 * w0.z + v1 * w1.z;
            plo.w += v0 * w0.w + v1 * w1.w;
            phi.x += v2 * w0.x + v3 * w1.x;
            phi.y += v2 * w0.y + v3 * w1.y;
            phi.z += v2 * w0.z + v3 * w1.z;
            phi.w += v2 * w0.w + v3 * w1.w;
        }
#pragma unroll
        for (int m = 1; m <= 2; m <<= 1) {
            plo.x += __shfl_xor_sync(0xffffffffu, plo.x, m);
            plo.y += __shfl_xor_sync(0xffffffffu, plo.y, m);
            plo.z += __shfl_xor_sync(0xffffffffu, plo.z, m);
            plo.w += __shfl_xor_sync(0xffffffffu, plo.w, m);
            phi.x += __shfl_xor_sync(0xffffffffu, phi.x, m);
            phi.y += __shfl_xor_sync(0xffffffffu, phi.y, m);
            phi.z += __shfl_xor_sync(0xffffffffu, phi.z, m);
            phi.w += __shfl_xor_sync(0xffffffffu, phi.w, m);
        }
        if (t == 0) {
            int r = m_base + mi * 16 + g;
            int ng = wid >> 2;
            *(float4*)&part[(ng * BM + r) * 4] = plo;
            *(float4*)&part[(ng * BM + r + 8) * 4] = phi;
        }
    }
    __syncthreads();

    if (tid < BM) {
        int ge = tile0 + tid;
        float4 o = make_float4(b3s[0], b3s[1], b3s[2], b3s[3]);
#pragma unroll
        for (int ng = 0; ng < 4; ng++) {
            float4 pv = *(const float4*)&part[(ng * BM + tid) * 4];
            o.x += pv.x; o.y += pv.y; o.z += pv.z; o.w += pv.w;
        }
        if (ge < E) *(float4*)&out[ge * 4] = o;
    }
}

// ---------------------------------------------------------------------------
extern "C" void kernel_launch(void* const* d_in, const int* in_sizes, int n_in,
                              void* d_out, int out_size) {
    const float* x   = (const float*)d_in[0];
    const float* pos = (const float*)d_in[1];
    const int*   ei  = (const int*)  d_in[2];
    const float* Wa  = (const float*)d_in[3];
    const float* ba  = (const float*)d_in[4];
    const float* Wp  = (const float*)d_in[5];
    const float* bp  = (const float*)d_in[6];
    const float* W1  = (const float*)d_in[7];
    const float* b1  = (const float*)d_in[8];
    const float* W2  = (const float*)d_in[9];
    const float* b2  = (const float*)d_in[10];
    const float* W3  = (const float*)d_in[11];
    const float* b3  = (const float*)d_in[12];
    float* out = (float*)d_out;

    int N = in_sizes[0] / 16;
    int E = in_sizes[2] / 2;

    weight_prod<<<2, 128>>>(Wa, ba, Wp, bp, W1);
    prep_w2<<<4, 256>>>(W2);
    node_h_kernel<<<(N + NPB - 1) / NPB, 128>>>(x, pos, N);
    edge_mlp7<<<(E + BM - 1) / BM, THREADS>>>(
        pos, ei, W1, b1, b2, W3, b3, out, E);
}

// round 13
// speedup vs baseline: 2.3531x; 1.0115x over previous
#include <cuda_runtime.h>
#include <cuda_fp16.h>
#include <math.h>
#include <stdint.h>

#define HID 128
#define BM  128
#define THREADS 512
#define NPB 32
#define N_NODES_MAX 100000

__device__ __half g_hsrc[N_NODES_MAX * HID];   // node_emb @ W1[0:128]
__device__ __half g_htgt[N_NODES_MAX * HID];   // node_emb @ W1[128:256]
__device__ __half g_w2h[4 * 4096];             // W2 chunks, uint4-paired frags
__device__ float  g_wx[2][16 * 128];
__device__ float  g_wp[2][3 * 128];
__device__ float  g_cb[2][128];

// fp16x2 silu: 0.5z(1+tanh(z/2)) — 1 MUFU per 2 values
__device__ __forceinline__ __half2 h2_silu(__half2 z) {
    __half2 hz = __hmul2(z, __float2half2_rn(0.5f));
    uint32_t th, hzin = *(uint32_t*)&hz;
    asm("tanh.approx.f16x2 %0, %1;" : "=r"(th) : "r"(hzin));
    return __hfma2(hz, *(__half2*)&th, hz);
}
__device__ __forceinline__ void mma16(float4& d, uint32_t a0, uint32_t a1,
                                      uint32_t a2, uint32_t a3,
                                      uint32_t b0, uint32_t b1) {
    asm volatile(
        "mma.sync.aligned.m16n8k16.row.col.f32.f16.f16.f32 "
        "{%0,%1,%2,%3},{%4,%5,%6,%7},{%8,%9},{%0,%1,%2,%3};"
        : "+f"(d.x), "+f"(d.y), "+f"(d.z), "+f"(d.w)
        : "r"(a0), "r"(a1), "r"(a2), "r"(a3), "r"(b0), "r"(b1));
}
__device__ __forceinline__ void ldm4(uint32_t& a0, uint32_t& a1,
                                     uint32_t& a2, uint32_t& a3, uint32_t addr) {
    asm volatile("ldmatrix.sync.aligned.m8n8.x4.shared.b16 {%0,%1,%2,%3},[%4];"
                 : "=r"(a0), "=r"(a1), "=r"(a2), "=r"(a3) : "r"(addr));
}
// swizzled 16B-chunk position within a 256B row (stays inside its 128B half)
__device__ __forceinline__ int sw_pos(int row, int cc) {
    return (cc & 8) + ((cc & 7) ^ (row & 7));
}

// ------------- Kernel 1: merged weight prep ---------------------------------
// blocks 0-1: weight products (fp32); blocks 2-5: W2 fragment packing
__global__ void prep_all(const float* __restrict__ Wa,
                         const float* __restrict__ ba,
                         const float* __restrict__ Wp,
                         const float* __restrict__ bp,
                         const float* __restrict__ W1,
                         const float* __restrict__ W2) {
    if (blockIdx.x < 2) {
        __shared__ float swa[16 * 128];
        __shared__ float swp[3 * 128];
        __shared__ float sb[128];
        int p = blockIdx.x;
        int tid = threadIdx.x;
        for (int i = tid; i < 16 * 128; i += 256) swa[i] = Wa[i];
        for (int i = tid; i < 3 * 128; i += 256) swp[i] = Wp[i];
        if (tid < 128) sb[tid] = ba[tid] + bp[tid];
        __syncthreads();
        if (tid < 128) {
            int j = tid;
            float ax[16];
#pragma unroll
            for (int i = 0; i < 16; i++) ax[i] = 0.f;
            float ap[3] = {0.f, 0.f, 0.f};
            float ac = 0.f;
            for (int k = 0; k < 128; k++) {
                float w = W1[(p * 128 + k) * 128 + j];
#pragma unroll
                for (int i = 0; i < 16; i++) ax[i] += swa[i * 128 + k] * w;
#pragma unroll
                for (int i = 0; i < 3; i++) ap[i] += swp[i * 128 + k] * w;
                ac += sb[k] * w;
            }
#pragma unroll
            for (int i = 0; i < 16; i++) g_wx[p][i * 128 + j] = ax[i];
#pragma unroll
            for (int i = 0; i < 3; i++) g_wp[p][i * 128 + j] = ap[i];
            g_cb[p][j] = ac;
        }
    } else {
        int c = blockIdx.x - 2;    // k32 chunk
        __half* dst = g_w2h + c * 4096;
        for (int idx = threadIdx.x; idx < 4096; idx += 256) {
            int u = idx & 3;
            int s = (idx >> 2) & 1;
            int t = (idx >> 3) & 3;
            int n = idx >> 5;
            int kl = s * 16 + ((u >> 1) << 3) + 2 * t + (u & 1);
            dst[idx] = __float2half(W2[(c * 32 + kl) * 128 + n]);
        }
    }
}

// ------------- Kernel 2: per-node h_src / h_tgt ------------------------------
__global__ void node_h_kernel(const float* __restrict__ x,
                              const float* __restrict__ pos, int N) {
    int j = threadIdx.x;
    float wx0[16], wx1[16], wp0[3], wp1[3];
#pragma unroll
    for (int i = 0; i < 16; i++) {
        wx0[i] = g_wx[0][i * 128 + j];
        wx1[i] = g_wx[1][i * 128 + j];
    }
#pragma unroll
    for (int i = 0; i < 3; i++) {
        wp0[i] = g_wp[0][i * 128 + j];
        wp1[i] = g_wp[1][i * 128 + j];
    }
    float c0 = g_cb[0][j], c1 = g_cb[1][j];

    __shared__ float xs[NPB][16];
    __shared__ float ps[NPB][3];
    int n0 = blockIdx.x * NPB;
    for (int i = j; i < NPB * 16; i += 128) {
        int n = n0 + (i >> 4);
        xs[i >> 4][i & 15] = (n < N) ? x[n * 16 + (i & 15)] : 0.0f;
    }
    for (int i = j; i < NPB * 3; i += 128) {
        int n = n0 + i / 3;
        ps[i / 3][i % 3] = (n < N) ? pos[n * 3 + i % 3] : 0.0f;
    }
    __syncthreads();
    for (int n = 0; n < NPB; n++) {
        if (n0 + n >= N) break;
        float s0 = c0, s1 = c1;
#pragma unroll
        for (int i = 0; i < 16; i++) {
            s0 += xs[n][i] * wx0[i];
            s1 += xs[n][i] * wx1[i];
        }
#pragma unroll
        for (int i = 0; i < 3; i++) {
            s0 += ps[n][i] * wp0[i];
            s1 += ps[n][i] * wp1[i];
        }
        g_hsrc[(n0 + n) * HID + j] = __float2half(s0);
        g_htgt[(n0 + n) * HID + j] = __float2half(s1);
    }
}

// ------------- Kernel 3: edge MLP (fp16x2 silu, packed B) -------------------
__global__ void __launch_bounds__(THREADS, 2)
edge_mlp8(const float* __restrict__ pos, const int* __restrict__ ei,
          const float* __restrict__ W1, const float* __restrict__ b1,
          const float* __restrict__ b2,
          const float* __restrict__ W3, const float* __restrict__ b3,
          float* __restrict__ out, int E) {
    __shared__ __align__(16) __half hs[BM * HID];        // 32 KB, swizzled
    __shared__ __align__(16) float part[4 * BM * 4];     // 8 KB
    __shared__ int   soff[BM], doff[BM];
    __shared__ float dist[BM];
    __shared__ __half2 w256h[64], sb1h[64];
    __shared__ float sb2[128], w3s[512], b3s[4];

    const uint32_t hsu = (uint32_t)__cvta_generic_to_shared(hs);
    const int tid  = threadIdx.x;
    const int lane = tid & 31;
    const int wid  = tid >> 5;               // 0..15
    const int m_base = (wid & 3) * 32;       // 4 m-groups of 32 rows
    const int n_warp = (wid >> 2) * 32;      // 4 n-groups of 32 cols
    const int g = lane >> 2;
    const int t = lane & 3;
    const int tile0 = blockIdx.x * BM;

    // ---- setup ----
    w3s[tid] = W3[tid];                      // 512 threads, 512 values
    if (tid < BM) {
        int ge = tile0 + tid; if (ge >= E) ge = E - 1;
        int s = ei[ge], d = ei[E + ge];
        soff[tid] = s * HID;
        doff[tid] = d * HID;
        float dx = pos[s * 3 + 0] - pos[d * 3 + 0];
        float dy = pos[s * 3 + 1] - pos[d * 3 + 1];
        float dz = pos[s * 3 + 2] - pos[d * 3 + 2];
        dist[tid] = sqrtf(dx * dx + dy * dy + dz * dz);
    } else if (tid < 192) {
        int c = tid - 128;                    // 0..63
        w256h[c] = __floats2half2_rn(W1[256 * 128 + 2 * c],
                                     W1[256 * 128 + 2 * c + 1]);
        sb1h[c]  = __floats2half2_rn(b1[2 * c], b1[2 * c + 1]);
    } else if (tid < 320) {
        sb2[tid - 192] = b2[tid - 192];
    }
    if (tid < 4) b3s[tid] = b3[tid];
    __syncthreads();

    // ---- conv: coalesced gather, all-fp16 silu -> hs ------------------------
    {
        const int g2 = lane >> 3;            // row within quad
        const int sub = lane & 7;            // 16B chunk within half-line
        const int rbase = wid * 8;
#pragma unroll
        for (int it = 0; it < 4; it++) {
            int half = it & 1;
            int rq = it >> 1;                // 0..1
            int row = rbase + rq * 4 + g2;
            uint4 av = *(const uint4*)(g_hsrc + soff[row] + half * 64 + sub * 8);
            uint4 bv = *(const uint4*)(g_htgt + doff[row] + half * 64 + sub * 8);
            __half2 dd2 = __float2half2_rn(dist[row]);
            int cc = half * 8 + sub;
            int h2b = cc * 4;
            const __half2* ah = (const __half2*)&av;
            const __half2* bh = (const __half2*)&bv;
            uint4 ov;
            __half2* oh = (__half2*)&ov;
#pragma unroll
            for (int jj = 0; jj < 4; jj++) {
                __half2 z = __hfma2(dd2, w256h[h2b + jj],
                                    __hadd2(__hadd2(ah[jj], bh[jj]), sb1h[h2b + jj]));
                oh[jj] = h2_silu(z);
            }
            *(uint4*)((char*)hs + row * 256 + (sw_pos(row, cc) << 4)) = ov;
        }
    }
    __syncthreads();

    // ---- GEMM2: h1 @ W2 (K=128), warp tile 32x32, packed B frags -----------
    float4 acc[2][4];
#pragma unroll
    for (int i = 0; i < 2; i++)
#pragma unroll
        for (int j = 0; j < 4; j++) acc[i][j] = make_float4(0.f, 0.f, 0.f, 0.f);
#pragma unroll
    for (int c = 0; c < 4; c++) {
        const __half* Bp = g_w2h + c * 4096;
        uint4 bf[4];
#pragma unroll
        for (int ni = 0; ni < 4; ni++) {
            int n = n_warp + ni * 8 + g;
            bf[ni] = *(const uint4*)(Bp + (n * 4 + t) * 8);
        }
#pragma unroll
        for (int s = 0; s < 2; s++) {
            int sg = c * 2 + s;
#pragma unroll
            for (int mi = 0; mi < 2; mi++) {
                int lrow = m_base + mi * 16 + (lane & 7) + (lane & 8);
                int cc = sg * 2 + (lane >> 4);
                uint32_t addr = hsu + lrow * 256 + (sw_pos(lrow, cc) << 4);
                uint32_t a0, a1, a2, a3;
                ldm4(a0, a1, a2, a3, addr);
#pragma unroll
                for (int ni = 0; ni < 4; ni++) {
                    uint32_t b0 = s ? bf[ni].z : bf[ni].x;
                    uint32_t b1v = s ? bf[ni].w : bf[ni].y;
                    mma16(acc[mi][ni], a0, a1, a2, a3, b0, b1v);
                }
            }
        }
    }

    // ---- epilogue: fp16x2 silu(D2+b2), GEMM3 dot, quad shfl reduce ---------
#pragma unroll
    for (int mi = 0; mi < 2; mi++) {
        float4 plo = make_float4(0.f, 0.f, 0.f, 0.f);
        float4 phi = make_float4(0.f, 0.f, 0.f, 0.f);
#pragma unroll
        for (int ni = 0; ni < 4; ni++) {
            int c0 = n_warp + ni * 8 + 2 * t;
            float2 bb = *(const float2*)&sb2[c0];
            float4 a = acc[mi][ni];
            __half2 zlo = __floats2half2_rn(a.x + bb.x, a.y + bb.y);
            __half2 zhi = __floats2half2_rn(a.z + bb.x, a.w + bb.y);
            float2 vlo = __half22float2(h2_silu(zlo));
            float2 vhi = __half22float2(h2_silu(zhi));
            float4 w0 = *(const float4*)&w3s[c0 * 4];
            float4 w1 = *(const float4*)&w3s[(c0 + 1) * 4];
            plo.x += vlo.x * w0.x + vlo.y * w1.x;
            plo.y += vlo.x * w0.y + vlo.y * w1.y;
            plo.z += vlo.x * w0.z + vlo.y * w1.z;
            plo.w += vlo.x * w0.w + vlo.y * w1.w;
            phi.x += vhi.x * w0.x + vhi.y * w1.x;
            phi.y += vhi.x * w0.y + vhi.y * w1.y;
            phi.z += vhi.x * w0.z + vhi.y * w1.z;
            phi.w += vhi.x * w0.w + vhi.y * w1.w;
        }
#pragma unroll
        for (int m = 1; m <= 2; m <<= 1) {
            plo.x += __shfl_xor_sync(0xffffffffu, plo.x, m);
            plo.y += __shfl_xor_sync(0xffffffffu, plo.y, m);
            plo.z += __shfl_xor_sync(0xffffffffu, plo.z, m);
            plo.w += __shfl_xor_sync(0xffffffffu, plo.w, m);
            phi.x += __shfl_xor_sync(0xffffffffu, phi.x, m);
            phi.y += __shfl_xor_sync(0xffffffffu, phi.y, m);
            phi.z += __shfl_xor_sync(0xffffffffu, phi.z, m);
            phi.w += __shfl_xor_sync(0xffffffffu, phi.w, m);
        }
        if (t == 0) {
            int r = m_base + mi * 16 + g;
            int ng = wid >> 2;
            *(float4*)&part[(ng * BM + r) * 4] = plo;
            *(float4*)&part[(ng * BM + r + 8) * 4] = phi;
        }
    }
    __syncthreads();

    if (tid < BM) {
        int ge = tile0 + tid;
        float4 o = make_float4(b3s[0], b3s[1], b3s[2], b3s[3]);
#pragma unroll
        for (int ng = 0; ng < 4; ng++) {
            float4 pv = *(const float4*)&part[(ng * BM + tid) * 4];
            o.x += pv.x; o.y += pv.y; o.z += pv.z; o.w += pv.w;
        }
        if (ge < E) *(float4*)&out[ge * 4] = o;
    }
}

// ---------------------------------------------------------------------------
extern "C" void kernel_launch(void* const* d_in, const int* in_sizes, int n_in,
                              void* d_out, int out_size) {
    const float* x   = (const float*)d_in[0];
    const float* pos = (const float*)d_in[1];
    const int*   ei  = (const int*)  d_in[2];
    const float* Wa  = (const float*)d_in[3];
    const float* ba  = (const float*)d_in[4];
    const float* Wp  = (const float*)d_in[5];
    const float* bp  = (const float*)d_in[6];
    const float* W1  = (const float*)d_in[7];
    const float* b1  = (const float*)d_in[8];
    const float* W2  = (const float*)d_in[9];
    const float* b2  = (const float*)d_in[10];
    const float* W3  = (const float*)d_in[11];
    const float* b3  = (const float*)d_in[12];
    float* out = (float*)d_out;

    int N = in_sizes[0] / 16;
    int E = in_sizes[2] / 2;

    prep_all<<<6, 256>>>(Wa, ba, Wp, bp, W1, W2);
    node_h_kernel<<<(N + NPB - 1) / NPB, 128>>>(x, pos, N);
    edge_mlp8<<<(E + BM - 1) / BM, THREADS>>>(
        pos, ei, W1, b1, b2, W3, b3, out, E);
}

// round 14
// speedup vs baseline: 2.5541x; 1.0854x over previous
#include <cuda_runtime.h>
#include <cuda_fp16.h>
#include <math.h>
#include <stdint.h>

#define HID 128
#define BM  128
#define THREADS 512
#define NPB 32
#define N_NODES_MAX 100000

__device__ __half g_hsrc[N_NODES_MAX * HID];   // node_emb @ W1[0:128]
__device__ __half g_htgt[N_NODES_MAX * HID];   // node_emb @ W1[128:256]
__device__ __half g_w2h[4 * 4096];             // W2 chunks, uint4-paired frags
__device__ float  g_wx[2][16 * 128];
__device__ float  g_wp[2][3 * 128];
__device__ float  g_cb[2][128];

// fp16x2 silu: 0.5z(1+tanh(z/2)) — 1 MUFU per 2 values
__device__ __forceinline__ __half2 h2_silu(__half2 z) {
    __half2 hz = __hmul2(z, __float2half2_rn(0.5f));
    uint32_t th, hzin = *(uint32_t*)&hz;
    asm("tanh.approx.f16x2 %0, %1;" : "=r"(th) : "r"(hzin));
    return __hfma2(hz, *(__half2*)&th, hz);
}
__device__ __forceinline__ void mma16(float4& d, uint32_t a0, uint32_t a1,
                                      uint32_t a2, uint32_t a3,
                                      uint32_t b0, uint32_t b1) {
    asm volatile(
        "mma.sync.aligned.m16n8k16.row.col.f32.f16.f16.f32 "
        "{%0,%1,%2,%3},{%4,%5,%6,%7},{%8,%9},{%0,%1,%2,%3};"
        : "+f"(d.x), "+f"(d.y), "+f"(d.z), "+f"(d.w)
        : "r"(a0), "r"(a1), "r"(a2), "r"(a3), "r"(b0), "r"(b1));
}
__device__ __forceinline__ void ldm4(uint32_t& a0, uint32_t& a1,
                                     uint32_t& a2, uint32_t& a3, uint32_t addr) {
    asm volatile("ldmatrix.sync.aligned.m8n8.x4.shared.b16 {%0,%1,%2,%3},[%4];"
                 : "=r"(a0), "=r"(a1), "=r"(a2), "=r"(a3) : "r"(addr));
}
// swizzled 16B-chunk position within a 256B row (stays inside its 128B half)
__device__ __forceinline__ int sw_pos(int row, int cc) {
    return (cc & 8) + ((cc & 7) ^ (row & 7));
}

// ------------- Kernel 1: merged weight prep (k-parallel products) -----------
// blocks 0-1: weight products (4-way k-split, smem reduce); 2-5: W2 packing
__global__ void __launch_bounds__(512)
prep_all(const float* __restrict__ Wa, const float* __restrict__ ba,
         const float* __restrict__ Wp, const float* __restrict__ bp,
         const float* __restrict__ W1, const float* __restrict__ W2) {
    if (blockIdx.x < 2) {
        __shared__ float swa[16 * 128];
        __shared__ float swp[3 * 128];
        __shared__ float sb[128];
        __shared__ float red[4][20][128];
        int p = blockIdx.x;
        int tid = threadIdx.x;
        int j = tid & 127;
        int kg = tid >> 7;          // 0..3
        for (int i = tid; i < 16 * 128; i += 512) swa[i] = Wa[i];
        for (int i = tid; i < 3 * 128; i += 512) swp[i] = Wp[i];
        if (tid < 128) sb[tid] = ba[tid] + bp[tid];
        __syncthreads();

        float ax[16];
#pragma unroll
        for (int i = 0; i < 16; i++) ax[i] = 0.f;
        float ap[3] = {0.f, 0.f, 0.f};
        float ac = 0.f;
#pragma unroll 4
        for (int kk = 0; kk < 32; kk++) {
            int k = kg * 32 + kk;
            float w = W1[(p * 128 + k) * 128 + j];
#pragma unroll
            for (int i = 0; i < 16; i++) ax[i] += swa[i * 128 + k] * w;
#pragma unroll
            for (int i = 0; i < 3; i++) ap[i] += swp[i * 128 + k] * w;
            ac += sb[k] * w;
        }
#pragma unroll
        for (int i = 0; i < 16; i++) red[kg][i][j] = ax[i];
#pragma unroll
        for (int i = 0; i < 3; i++) red[kg][16 + i][j] = ap[i];
        red[kg][19][j] = ac;
        __syncthreads();
        // reduce: 512 threads over 20*128 = 2560 entries
        for (int idx = tid; idx < 20 * 128; idx += 512) {
            int r = idx >> 7, jj = idx & 127;
            float s = red[0][r][jj] + red[1][r][jj] + red[2][r][jj] + red[3][r][jj];
            if (r < 16)      g_wx[p][r * 128 + jj] = s;
            else if (r < 19) g_wp[p][(r - 16) * 128 + jj] = s;
            else             g_cb[p][jj] = s;
        }
    } else {
        int c = blockIdx.x - 2;    // k32 chunk
        __half* dst = g_w2h + c * 4096;
        for (int idx = threadIdx.x; idx < 4096; idx += 512) {
            int u = idx & 3;
            int s = (idx >> 2) & 1;
            int t = (idx >> 3) & 3;
            int n = idx >> 5;
            int kl = s * 16 + ((u >> 1) << 3) + 2 * t + (u & 1);
            dst[idx] = __float2half(W2[(c * 32 + kl) * 128 + n]);
        }
    }
}

// ------------- Kernel 2: per-node h_src / h_tgt ------------------------------
__global__ void node_h_kernel(const float* __restrict__ x,
                              const float* __restrict__ pos, int N) {
    int j = threadIdx.x;
    float wx0[16], wx1[16], wp0[3], wp1[3];
#pragma unroll
    for (int i = 0; i < 16; i++) {
        wx0[i] = g_wx[0][i * 128 + j];
        wx1[i] = g_wx[1][i * 128 + j];
    }
#pragma unroll
    for (int i = 0; i < 3; i++) {
        wp0[i] = g_wp[0][i * 128 + j];
        wp1[i] = g_wp[1][i * 128 + j];
    }
    float c0 = g_cb[0][j], c1 = g_cb[1][j];

    __shared__ float xs[NPB][16];
    __shared__ float ps[NPB][3];
    int n0 = blockIdx.x * NPB;
    for (int i = j; i < NPB * 16; i += 128) {
        int n = n0 + (i >> 4);
        xs[i >> 4][i & 15] = (n < N) ? x[n * 16 + (i & 15)] : 0.0f;
    }
    for (int i = j; i < NPB * 3; i += 128) {
        int n = n0 + i / 3;
        ps[i / 3][i % 3] = (n < N) ? pos[n * 3 + i % 3] : 0.0f;
    }
    __syncthreads();
    for (int n = 0; n < NPB; n++) {
        if (n0 + n >= N) break;
        float s0 = c0, s1 = c1;
#pragma unroll
        for (int i = 0; i < 16; i++) {
            s0 += xs[n][i] * wx0[i];
            s1 += xs[n][i] * wx1[i];
        }
#pragma unroll
        for (int i = 0; i < 3; i++) {
            s0 += ps[n][i] * wp0[i];
            s1 += ps[n][i] * wp1[i];
        }
        g_hsrc[(n0 + n) * HID + j] = __float2half(s0);
        g_htgt[(n0 + n) * HID + j] = __float2half(s1);
    }
}

// ------------- Kernel 3: edge MLP (fp16x2 silu, hoisted epilogue) -----------
__global__ void __launch_bounds__(THREADS, 2)
edge_mlp9(const float* __restrict__ pos, const int* __restrict__ ei,
          const float* __restrict__ W1, const float* __restrict__ b1,
          const float* __restrict__ b2,
          const float* __restrict__ W3, const float* __restrict__ b3,
          float* __restrict__ out, int E) {
    __shared__ __align__(16) __half hs[BM * HID];        // 32 KB, swizzled
    __shared__ __align__(16) float part[4 * BM * 4];     // 8 KB
    __shared__ int   soff[BM], doff[BM];
    __shared__ float dist[BM];
    __shared__ __half2 w256h[64], sb1h[64];
    __shared__ float sb2[128], w3s[512], b3s[4];

    const uint32_t hsu = (uint32_t)__cvta_generic_to_shared(hs);
    const int tid  = threadIdx.x;
    const int lane = tid & 31;
    const int wid  = tid >> 5;               // 0..15
    const int m_base = (wid & 3) * 32;       // 4 m-groups of 32 rows
    const int n_warp = (wid >> 2) * 32;      // 4 n-groups of 32 cols
    const int g = lane >> 2;
    const int t = lane & 3;
    const int tile0 = blockIdx.x * BM;

    // ---- setup ----
    w3s[tid] = W3[tid];
    if (tid < BM) {
        int ge = tile0 + tid; if (ge >= E) ge = E - 1;
        int s = ei[ge], d = ei[E + ge];
        soff[tid] = s * HID;
        doff[tid] = d * HID;
        float dx = pos[s * 3 + 0] - pos[d * 3 + 0];
        float dy = pos[s * 3 + 1] - pos[d * 3 + 1];
        float dz = pos[s * 3 + 2] - pos[d * 3 + 2];
        dist[tid] = sqrtf(dx * dx + dy * dy + dz * dz);
    } else if (tid < 192) {
        int c = tid - 128;
        w256h[c] = __floats2half2_rn(W1[256 * 128 + 2 * c],
                                     W1[256 * 128 + 2 * c + 1]);
        sb1h[c]  = __floats2half2_rn(b1[2 * c], b1[2 * c + 1]);
    } else if (tid < 320) {
        sb2[tid - 192] = b2[tid - 192];
    }
    if (tid < 4) b3s[tid] = b3[tid];
    __syncthreads();

    // ---- conv: coalesced gather, all-fp16 silu -> hs ------------------------
    {
        const int g2 = lane >> 3;
        const int sub = lane & 7;
        const int rbase = wid * 8;
#pragma unroll
        for (int it = 0; it < 4; it++) {
            int half = it & 1;
            int rq = it >> 1;
            int row = rbase + rq * 4 + g2;
            uint4 av = *(const uint4*)(g_hsrc + soff[row] + half * 64 + sub * 8);
            uint4 bv = *(const uint4*)(g_htgt + doff[row] + half * 64 + sub * 8);
            __half2 dd2 = __float2half2_rn(dist[row]);
            int cc = half * 8 + sub;
            int h2b = cc * 4;
            const __half2* ah = (const __half2*)&av;
            const __half2* bh = (const __half2*)&bv;
            uint4 ov;
            __half2* oh = (__half2*)&ov;
#pragma unroll
            for (int jj = 0; jj < 4; jj++) {
                __half2 z = __hfma2(dd2, w256h[h2b + jj],
                                    __hadd2(__hadd2(ah[jj], bh[jj]), sb1h[h2b + jj]));
                oh[jj] = h2_silu(z);
            }
            *(uint4*)((char*)hs + row * 256 + (sw_pos(row, cc) << 4)) = ov;
        }
    }
    __syncthreads();

    // ---- GEMM2: h1 @ W2 (K=128), warp tile 32x32, packed B frags -----------
    float4 acc[2][4];
#pragma unroll
    for (int i = 0; i < 2; i++)
#pragma unroll
        for (int j = 0; j < 4; j++) acc[i][j] = make_float4(0.f, 0.f, 0.f, 0.f);
#pragma unroll
    for (int c = 0; c < 4; c++) {
        const __half* Bp = g_w2h + c * 4096;
        uint4 bf[4];
#pragma unroll
        for (int ni = 0; ni < 4; ni++) {
            int n = n_warp + ni * 8 + g;
            bf[ni] = *(const uint4*)(Bp + (n * 4 + t) * 8);
        }
#pragma unroll
        for (int s = 0; s < 2; s++) {
            int sg = c * 2 + s;
#pragma unroll
            for (int mi = 0; mi < 2; mi++) {
                int lrow = m_base + mi * 16 + (lane & 7) + (lane & 8);
                int cc = sg * 2 + (lane >> 4);
                uint32_t addr = hsu + lrow * 256 + (sw_pos(lrow, cc) << 4);
                uint32_t a0, a1, a2, a3;
                ldm4(a0, a1, a2, a3, addr);
#pragma unroll
                for (int ni = 0; ni < 4; ni++) {
                    uint32_t b0 = s ? bf[ni].z : bf[ni].x;
                    uint32_t b1v = s ? bf[ni].w : bf[ni].y;
                    mma16(acc[mi][ni], a0, a1, a2, a3, b0, b1v);
                }
            }
        }
    }

    // ---- epilogue: fp16x2 silu(D2+b2), GEMM3 dot (hoisted w3), shfl --------
    {
        float4 plo[2] = {make_float4(0.f, 0.f, 0.f, 0.f),
                         make_float4(0.f, 0.f, 0.f, 0.f)};
        float4 phi[2] = {make_float4(0.f, 0.f, 0.f, 0.f),
                         make_float4(0.f, 0.f, 0.f, 0.f)};
#pragma unroll
        for (int ni = 0; ni < 4; ni++) {
            int c0 = n_warp + ni * 8 + 2 * t;
            float2 bb = *(const float2*)&sb2[c0];
            float4 w0 = *(const float4*)&w3s[c0 * 4];
            float4 w1 = *(const float4*)&w3s[(c0 + 1) * 4];
#pragma unroll
            for (int mi = 0; mi < 2; mi++) {
                float4 a = acc[mi][ni];
                __half2 zlo = __floats2half2_rn(a.x + bb.x, a.y + bb.y);
                __half2 zhi = __floats2half2_rn(a.z + bb.x, a.w + bb.y);
                float2 vlo = __half22float2(h2_silu(zlo));
                float2 vhi = __half22float2(h2_silu(zhi));
                plo[mi].x += vlo.x * w0.x + vlo.y * w1.x;
                plo[mi].y += vlo.x * w0.y + vlo.y * w1.y;
                plo[mi].z += vlo.x * w0.z + vlo.y * w1.z;
                plo[mi].w += vlo.x * w0.w + vlo.y * w1.w;
                phi[mi].x += vhi.x * w0.x + vhi.y * w1.x;
                phi[mi].y += vhi.x * w0.y + vhi.y * w1.y;
                phi[mi].z += vhi.x * w0.z + vhi.y * w1.z;
                phi[mi].w += vhi.x * w0.w + vhi.y * w1.w;
            }
        }
#pragma unroll
        for (int mi = 0; mi < 2; mi++) {
#pragma unroll
            for (int m = 1; m <= 2; m <<= 1) {
                plo[mi].x += __shfl_xor_sync(0xffffffffu, plo[mi].x, m);
                plo[mi].y += __shfl_xor_sync(0xffffffffu, plo[mi].y, m);
                plo[mi].z += __shfl_xor_sync(0xffffffffu, plo[mi].z, m);
                plo[mi].w += __shfl_xor_sync(0xffffffffu, plo[mi].w, m);
                phi[mi].x += __shfl_xor_sync(0xffffffffu, phi[mi].x, m);
                phi[mi].y += __shfl_xor_sync(0xffffffffu, phi[mi].y, m);
                phi[mi].z += __shfl_xor_sync(0xffffffffu, phi[mi].z, m);
                phi[mi].w += __shfl_xor_sync(0xffffffffu, phi[mi].w, m);
            }
            if (t == 0) {
                int r = m_base + mi * 16 + g;
                int ng = wid >> 2;
                *(float4*)&part[(ng * BM + r) * 4] = plo[mi];
                *(float4*)&part[(ng * BM + r + 8) * 4] = phi[mi];
            }
        }
    }
    __syncthreads();

    if (tid < BM) {
        int ge = tile0 + tid;
        float4 o = make_float4(b3s[0], b3s[1], b3s[2], b3s[3]);
#pragma unroll
        for (int ng = 0; ng < 4; ng++) {
            float4 pv = *(const float4*)&part[(ng * BM + tid) * 4];
            o.x += pv.x; o.y += pv.y; o.z += pv.z; o.w += pv.w;
        }
        if (ge < E) *(float4*)&out[ge * 4] = o;
    }
}

// ---------------------------------------------------------------------------
extern "C" void kernel_launch(void* const* d_in, const int* in_sizes, int n_in,
                              void* d_out, int out_size) {
    const float* x   = (const float*)d_in[0];
    const float* pos = (const float*)d_in[1];
    const int*   ei  = (const int*)  d_in[2];
    const float* Wa  = (const float*)d_in[3];
    const float* ba  = (const float*)d_in[4];
    const float* Wp  = (const float*)d_in[5];
    const float* bp  = (const float*)d_in[6];
    const float* W1  = (const float*)d_in[7];
    const float* b1  = (const float*)d_in[8];
    const float* W2  = (const float*)d_in[9];
    const float* b2  = (const float*)d_in[10];
    const float* W3  = (const float*)d_in[11];
    const float* b3  = (const float*)d_in[12];
    float* out = (float*)d_out;

    int N = in_sizes[0] / 16;
    int E = in_sizes[2] / 2;

    prep_all<<<6, 512>>>(Wa, ba, Wp, bp, W1, W2);
    node_h_kernel<<<(N + NPB - 1) / NPB, 128>>>(x, pos, N);
    edge_mlp9<<<(E + BM - 1) / BM, THREADS>>>(
        pos, ei, W1, b1, b2, W3, b3, out, E);
}

// round 15
// speedup vs baseline: 2.5967x; 1.0167x over previous
#include <cuda_runtime.h>
#include <cuda_fp16.h>
#include <math.h>
#include <stdint.h>

#define HID 128
#define BM  128
#define THREADS 512
#define NPB 32
#define N_NODES_MAX 100000

__device__ __half g_hsrc[N_NODES_MAX * HID];   // node_emb @ W1[0:128]
__device__ __half g_htgt[N_NODES_MAX * HID];   // node_emb @ W1[128:256]
__device__ __half g_w2h[4 * 4096];             // W2 chunks, uint4-paired frags
__device__ float  g_wx[2][16 * 128];
__device__ float  g_wp[2][3 * 128];
__device__ float  g_cb[2][128];

// fp16x2 silu: 0.5z(1+tanh(z/2)) — 1 MUFU per 2 values
__device__ __forceinline__ __half2 h2_silu(__half2 z) {
    __half2 hz = __hmul2(z, __float2half2_rn(0.5f));
    uint32_t th, hzin = *(uint32_t*)&hz;
    asm("tanh.approx.f16x2 %0, %1;" : "=r"(th) : "r"(hzin));
    return __hfma2(hz, *(__half2*)&th, hz);
}
__device__ __forceinline__ void mma16(float4& d, uint32_t a0, uint32_t a1,
                                      uint32_t a2, uint32_t a3,
                                      uint32_t b0, uint32_t b1) {
    asm volatile(
        "mma.sync.aligned.m16n8k16.row.col.f32.f16.f16.f32 "
        "{%0,%1,%2,%3},{%4,%5,%6,%7},{%8,%9},{%0,%1,%2,%3};"
        : "+f"(d.x), "+f"(d.y), "+f"(d.z), "+f"(d.w)
        : "r"(a0), "r"(a1), "r"(a2), "r"(a3), "r"(b0), "r"(b1));
}
__device__ __forceinline__ void ldm4(uint32_t& a0, uint32_t& a1,
                                     uint32_t& a2, uint32_t& a3, uint32_t addr) {
    asm volatile("ldmatrix.sync.aligned.m8n8.x4.shared.b16 {%0,%1,%2,%3},[%4];"
                 : "=r"(a0), "=r"(a1), "=r"(a2), "=r"(a3) : "r"(addr));
}
// swizzled 16B-chunk position within a 256B row (stays inside its 128B half)
__device__ __forceinline__ int sw_pos(int row, int cc) {
    return (cc & 8) + ((cc & 7) ^ (row & 7));
}

// ------------- Kernel 1: merged weight prep (8-way k-split, 1024 thr) -------
// blocks 0-1: weight products; blocks 2-5: W2 fragment packing
__global__ void __launch_bounds__(1024)
prep_all(const float* __restrict__ Wa, const float* __restrict__ ba,
         const float* __restrict__ Wp, const float* __restrict__ bp,
         const float* __restrict__ W1, const float* __restrict__ W2) {
    extern __shared__ float red[];   // [8][20][128] = 80 KB (blocks 0-1 only)
    if (blockIdx.x < 2) {
        __shared__ float swa[16 * 128];
        __shared__ float swp[3 * 128];
        __shared__ float sb[128];
        int p = blockIdx.x;
        int tid = threadIdx.x;
        int j = tid & 127;
        int kg = tid >> 7;          // 0..7
        for (int i = tid; i < 16 * 128; i += 1024) swa[i] = Wa[i];
        for (int i = tid; i < 3 * 128; i += 1024) swp[i] = Wp[i];
        if (tid < 128) sb[tid] = ba[tid] + bp[tid];
        __syncthreads();

        float ax[16];
#pragma unroll
        for (int i = 0; i < 16; i++) ax[i] = 0.f;
        float ap[3] = {0.f, 0.f, 0.f};
        float ac = 0.f;
#pragma unroll
        for (int kk = 0; kk < 16; kk++) {
            int k = kg * 16 + kk;
            float w = W1[(p * 128 + k) * 128 + j];
#pragma unroll
            for (int i = 0; i < 16; i++) ax[i] += swa[i * 128 + k] * w;
#pragma unroll
            for (int i = 0; i < 3; i++) ap[i] += swp[i * 128 + k] * w;
            ac += sb[k] * w;
        }
#pragma unroll
        for (int i = 0; i < 16; i++) red[(kg * 20 + i) * 128 + j] = ax[i];
#pragma unroll
        for (int i = 0; i < 3; i++) red[(kg * 20 + 16 + i) * 128 + j] = ap[i];
        red[(kg * 20 + 19) * 128 + j] = ac;
        __syncthreads();
        // reduce: 1024 threads over 20*128 = 2560 entries, 8 partials each
        for (int idx = tid; idx < 20 * 128; idx += 1024) {
            int r = idx >> 7, jj = idx & 127;
            float s = 0.f;
#pragma unroll
            for (int kk = 0; kk < 8; kk++) s += red[(kk * 20 + r) * 128 + jj];
            if (r < 16)      g_wx[p][r * 128 + jj] = s;
            else if (r < 19) g_wp[p][(r - 16) * 128 + jj] = s;
            else             g_cb[p][jj] = s;
        }
    } else {
        int c = blockIdx.x - 2;    // k32 chunk
        __half* dst = g_w2h + c * 4096;
        for (int idx = threadIdx.x; idx < 4096; idx += 1024) {
            int u = idx & 3;
            int s = (idx >> 2) & 1;
            int t = (idx >> 3) & 3;
            int n = idx >> 5;
            int kl = s * 16 + ((u >> 1) << 3) + 2 * t + (u & 1);
            dst[idx] = __float2half(W2[(c * 32 + kl) * 128 + n]);
        }
    }
}

// ------------- Kernel 2: per-node h_src / h_tgt (unrolled) -------------------
__global__ void node_h_kernel(const float* __restrict__ x,
                              const float* __restrict__ pos, int N) {
    int j = threadIdx.x;
    float wx0[16], wx1[16], wp0[3], wp1[3];
#pragma unroll
    for (int i = 0; i < 16; i++) {
        wx0[i] = g_wx[0][i * 128 + j];
        wx1[i] = g_wx[1][i * 128 + j];
    }
#pragma unroll
    for (int i = 0; i < 3; i++) {
        wp0[i] = g_wp[0][i * 128 + j];
        wp1[i] = g_wp[1][i * 128 + j];
    }
    float c0 = g_cb[0][j], c1 = g_cb[1][j];

    __shared__ float xs[NPB][16];
    __shared__ float ps[NPB][3];
    int n0 = blockIdx.x * NPB;
    for (int i = j; i < NPB * 16; i += 128) {
        int n = n0 + (i >> 4);
        xs[i >> 4][i & 15] = (n < N) ? x[n * 16 + (i & 15)] : 0.0f;
    }
    for (int i = j; i < NPB * 3; i += 128) {
        int n = n0 + i / 3;
        ps[i / 3][i % 3] = (n < N) ? pos[n * 3 + i % 3] : 0.0f;
    }
    __syncthreads();
#pragma unroll 4
    for (int n = 0; n < NPB; n++) {
        float s0 = c0, s1 = c1;
#pragma unroll
        for (int i = 0; i < 16; i++) {
            s0 += xs[n][i] * wx0[i];
            s1 += xs[n][i] * wx1[i];
        }
#pragma unroll
        for (int i = 0; i < 3; i++) {
            s0 += ps[n][i] * wp0[i];
            s1 += ps[n][i] * wp1[i];
        }
        if (n0 + n < N) {
            g_hsrc[(n0 + n) * HID + j] = __float2half(s0);
            g_htgt[(n0 + n) * HID + j] = __float2half(s1);
        }
    }
}

// ------------- Kernel 3: edge MLP (fp16x2 silu, hoisted epilogue) -----------
__global__ void __launch_bounds__(THREADS, 2)
edge_mlp9(const float* __restrict__ pos, const int* __restrict__ ei,
          const float* __restrict__ W1, const float* __restrict__ b1,
          const float* __restrict__ b2,
          const float* __restrict__ W3, const float* __restrict__ b3,
          float* __restrict__ out, int E) {
    __shared__ __align__(16) __half hs[BM * HID];        // 32 KB, swizzled
    __shared__ __align__(16) float part[4 * BM * 4];     // 8 KB
    __shared__ int   soff[BM], doff[BM];
    __shared__ float dist[BM];
    __shared__ __half2 w256h[64], sb1h[64];
    __shared__ float sb2[128], w3s[512], b3s[4];

    const uint32_t hsu = (uint32_t)__cvta_generic_to_shared(hs);
    const int tid  = threadIdx.x;
    const int lane = tid & 31;
    const int wid  = tid >> 5;               // 0..15
    const int m_base = (wid & 3) * 32;       // 4 m-groups of 32 rows
    const int n_warp = (wid >> 2) * 32;      // 4 n-groups of 32 cols
    const int g = lane >> 2;
    const int t = lane & 3;
    const int tile0 = blockIdx.x * BM;

    // ---- setup ----
    w3s[tid] = W3[tid];
    if (tid < BM) {
        int ge = tile0 + tid; if (ge >= E) ge = E - 1;
        int s = ei[ge], d = ei[E + ge];
        soff[tid] = s * HID;
        doff[tid] = d * HID;
        float dx = pos[s * 3 + 0] - pos[d * 3 + 0];
        float dy = pos[s * 3 + 1] - pos[d * 3 + 1];
        float dz = pos[s * 3 + 2] - pos[d * 3 + 2];
        dist[tid] = sqrtf(dx * dx + dy * dy + dz * dz);
    } else if (tid < 192) {
        int c = tid - 128;
        w256h[c] = __floats2half2_rn(W1[256 * 128 + 2 * c],
                                     W1[256 * 128 + 2 * c + 1]);
        sb1h[c]  = __floats2half2_rn(b1[2 * c], b1[2 * c + 1]);
    } else if (tid < 320) {
        sb2[tid - 192] = b2[tid - 192];
    }
    if (tid < 4) b3s[tid] = b3[tid];
    __syncthreads();

    // ---- conv: coalesced gather, all-fp16 silu -> hs ------------------------
    {
        const int g2 = lane >> 3;
        const int sub = lane & 7;
        const int rbase = wid * 8;
#pragma unroll
        for (int it = 0; it < 4; it++) {
            int half = it & 1;
            int rq = it >> 1;
            int row = rbase + rq * 4 + g2;
            uint4 av = *(const uint4*)(g_hsrc + soff[row] + half * 64 + sub * 8);
            uint4 bv = *(const uint4*)(g_htgt + doff[row] + half * 64 + sub * 8);
            __half2 dd2 = __float2half2_rn(dist[row]);
            int cc = half * 8 + sub;
            int h2b = cc * 4;
            const __half2* ah = (const __half2*)&av;
            const __half2* bh = (const __half2*)&bv;
            uint4 ov;
            __half2* oh = (__half2*)&ov;
#pragma unroll
            for (int jj = 0; jj < 4; jj++) {
                __half2 z = __hfma2(dd2, w256h[h2b + jj],
                                    __hadd2(__hadd2(ah[jj], bh[jj]), sb1h[h2b + jj]));
                oh[jj] = h2_silu(z);
            }
            *(uint4*)((char*)hs + row * 256 + (sw_pos(row, cc) << 4)) = ov;
        }
    }
    __syncthreads();

    // ---- GEMM2: h1 @ W2 (K=128), warp tile 32x32, packed B frags -----------
    float4 acc[2][4];
#pragma unroll
    for (int i = 0; i < 2; i++)
#pragma unroll
        for (int j = 0; j < 4; j++) acc[i][j] = make_float4(0.f, 0.f, 0.f, 0.f);
#pragma unroll
    for (int c = 0; c < 4; c++) {
        const __half* Bp = g_w2h + c * 4096;
        uint4 bf[4];
#pragma unroll
        for (int ni = 0; ni < 4; ni++) {
            int n = n_warp + ni * 8 + g;
            bf[ni] = *(const uint4*)(Bp + (n * 4 + t) * 8);
        }
#pragma unroll
        for (int s = 0; s < 2; s++) {
            int sg = c * 2 + s;
#pragma unroll
            for (int mi = 0; mi < 2; mi++) {
                int lrow = m_base + mi * 16 + (lane & 7) + (lane & 8);
                int cc = sg * 2 + (lane >> 4);
                uint32_t addr = hsu + lrow * 256 + (sw_pos(lrow, cc) << 4);
                uint32_t a0, a1, a2, a3;
                ldm4(a0, a1, a2, a3, addr);
#pragma unroll
                for (int ni = 0; ni < 4; ni++) {
                    uint32_t b0 = s ? bf[ni].z : bf[ni].x;
                    uint32_t b1v = s ? bf[ni].w : bf[ni].y;
                    mma16(acc[mi][ni], a0, a1, a2, a3, b0, b1v);
                }
            }
        }
    }

    // ---- epilogue: fp16x2 silu(D2+b2), GEMM3 dot (hoisted w3), shfl --------
    {
        float4 plo[2] = {make_float4(0.f, 0.f, 0.f, 0.f),
                         make_float4(0.f, 0.f, 0.f, 0.f)};
        float4 phi[2] = {make_float4(0.f, 0.f, 0.f, 0.f),
                         make_float4(0.f, 0.f, 0.f, 0.f)};
#pragma unroll
        for (int ni = 0; ni < 4; ni++) {
            int c0 = n_warp + ni * 8 + 2 * t;
            float2 bb = *(const float2*)&sb2[c0];
            float4 w0 = *(const float4*)&w3s[c0 * 4];
            float4 w1 = *(const float4*)&w3s[(c0 + 1) * 4];
#pragma unroll
            for (int mi = 0; mi < 2; mi++) {
                float4 a = acc[mi][ni];
                __half2 zlo = __floats2half2_rn(a.x + bb.x, a.y + bb.y);
                __half2 zhi = __floats2half2_rn(a.z + bb.x, a.w + bb.y);
                float2 vlo = __half22float2(h2_silu(zlo));
                float2 vhi = __half22float2(h2_silu(zhi));
                plo[mi].x += vlo.x * w0.x + vlo.y * w1.x;
                plo[mi].y += vlo.x * w0.y + vlo.y * w1.y;
                plo[mi].z += vlo.x * w0.z + vlo.y * w1.z;
                plo[mi].w += vlo.x * w0.w + vlo.y * w1.w;
                phi[mi].x += vhi.x * w0.x + vhi.y * w1.x;
                phi[mi].y += vhi.x * w0.y + vhi.y * w1.y;
                phi[mi].z += vhi.x * w0.z + vhi.y * w1.z;
                phi[mi].w += vhi.x * w0.w + vhi.y * w1.w;
            }
        }
#pragma unroll
        for (int mi = 0; mi < 2; mi++) {
#pragma unroll
            for (int m = 1; m <= 2; m <<= 1) {
                plo[mi].x += __shfl_xor_sync(0xffffffffu, plo[mi].x, m);
                plo[mi].y += __shfl_xor_sync(0xffffffffu, plo[mi].y, m);
                plo[mi].z += __shfl_xor_sync(0xffffffffu, plo[mi].z, m);
                plo[mi].w += __shfl_xor_sync(0xffffffffu, plo[mi].w, m);
                phi[mi].x += __shfl_xor_sync(0xffffffffu, phi[mi].x, m);
                phi[mi].y += __shfl_xor_sync(0xffffffffu, phi[mi].y, m);
                phi[mi].z += __shfl_xor_sync(0xffffffffu, phi[mi].z, m);
                phi[mi].w += __shfl_xor_sync(0xffffffffu, phi[mi].w, m);
            }
            if (t == 0) {
                int r = m_base + mi * 16 + g;
                int ng = wid >> 2;
                *(float4*)&part[(ng * BM + r) * 4] = plo[mi];
                *(float4*)&part[(ng * BM + r + 8) * 4] = phi[mi];
            }
        }
    }
    __syncthreads();

    if (tid < BM) {
        int ge = tile0 + tid;
        float4 o = make_float4(b3s[0], b3s[1], b3s[2], b3s[3]);
#pragma unroll
        for (int ng = 0; ng < 4; ng++) {
            float4 pv = *(const float4*)&part[(ng * BM + tid) * 4];
            o.x += pv.x; o.y += pv.y; o.z += pv.z; o.w += pv.w;
        }
        if (ge < E) *(float4*)&out[ge * 4] = o;
    }
}

// ---------------------------------------------------------------------------
extern "C" void kernel_launch(void* const* d_in, const int* in_sizes, int n_in,
                              void* d_out, int out_size) {
    const float* x   = (const float*)d_in[0];
    const float* pos = (const float*)d_in[1];
    const int*   ei  = (const int*)  d_in[2];
    const float* Wa  = (const float*)d_in[3];
    const float* ba  = (const float*)d_in[4];
    const float* Wp  = (const float*)d_in[5];
    const float* bp  = (const float*)d_in[6];
    const float* W1  = (const float*)d_in[7];
    const float* b1  = (const float*)d_in[8];
    const float* W2  = (const float*)d_in[9];
    const float* b2  = (const float*)d_in[10];
    const float* W3  = (const float*)d_in[11];
    const float* b3  = (const float*)d_in[12];
    float* out = (float*)d_out;

    int N = in_sizes[0] / 16;
    int E = in_sizes[2] / 2;

    size_t prep_smem = 8 * 20 * 128 * sizeof(float);   // 80 KB
    cudaFuncSetAttribute(prep_all,
                         cudaFuncAttributeMaxDynamicSharedMemorySize,
                         (int)prep_smem);

    prep_all<<<6, 1024, prep_smem>>>(Wa, ba, Wp, bp, W1, W2);
    node_h_kernel<<<(N + NPB - 1) / NPB, 128>>>(x, pos, N);
    edge_mlp9<<<(E + BM - 1) / BM, THREADS>>>(
        pos, ei, W1, b1, b2, W3, b3, out, E);
}